// round 15
// baseline (speedup 1.0000x reference)
#include <cuda_runtime.h>

// Shapes: B=16, C=32, H1=W1=256, H2=W2=64
#define NCH   512
#define H1D   256
#define W1D   256
#define TW    64
#define HO    319                         // H1 + TW - 1
#define SARV  4096.0f
#define EPSV  1.1920928955078125e-07f     // float32 eps

#define KROWS 40
#define NCHNK ((HO + KROWS - 1) / KROWS)  // 8

// Precise sqrt/div epilogue (empirically fastest: ILP-rich FFMA expansion).
__device__ __forceinline__ void ncc_emit(float* __restrict__ op,
                                         float xv, float ws, float ws2,
                                         float mean, float ssd) {
    float num = xv - ws * mean;
    float wcr = ws2 - ws * ws * (1.0f / SARV);
    float den = sqrtf(fmaxf(wcr * ssd, 0.f));
    float r   = fmaxf(num, EPSV) / fmaxf(den, EPSV);
    *op = (den > EPSV) ? r : 0.f;
}

// ---------------------------------------------------------------------------
// 256 threads = 256 columns, 2 rows/iter, 40 rows per CTA. In-window-only
// sums. Vertical suffix snapshots stored only at k = 4j+3 (20 KB); suffixes
// reconstructed add-only from <=3 extra row loads. Warp suffix via
// (total - prefix) + own (exact at lane 31). Incremental row pointers.
// smem ~24KB -> 8 CTAs/SM.
// ---------------------------------------------------------------------------
__global__ __launch_bounds__(256, 7) void ncc_vh11(const float* __restrict__ f1,
                                                   const float* __restrict__ f2,
                                                   const float* __restrict__ xcg,
                                                   float* __restrict__ outg) {
    const int c  = blockIdx.y;
    const int i0 = blockIdx.x * KROWS;
    const int t  = threadIdx.x;
    const int lane = t & 31;
    const int w    = t >> 5;        // warp 0..7
    const int h    = w & 1;         // half within its 64-col block

    const float* __restrict__ x  = f1  + (size_t)c * (H1D * W1D);
    const float* __restrict__ p2 = f2  + (size_t)c * (TW * TW);
    const float* __restrict__ xc = xcg + (size_t)c * (HO * HO);
    float* __restrict__ op       = outg + (size_t)c * (HO * HO);

    __shared__ float  wred[16];                // warp sums / warp ssd sums
    __shared__ float2 snapQ[KROWS / 4][256];   // snapshots at k = 4j+3 only
    __shared__ float4 wtot4[8];                // per-warp totals (A,A2,B,B2)
    __shared__ float2 SvA[256], SvB[256];      // published 64-block suffixes

    // ---- per-channel stats of feat_2 (warp-shfl reduction, 2 barriers) ----
    float mean, ssd;
    {
        float vals[16];
        float s = 0.f;
#pragma unroll
        for (int k = 0; k < 16; ++k) {
            vals[k] = p2[t + 256 * k];
            s += vals[k];
        }
#pragma unroll
        for (int d = 16; d; d >>= 1) s += __shfl_xor_sync(0xffffffffu, s, d);
        if (lane == 0) wred[w] = s;
        __syncthreads();
        float tot = 0.f;
#pragma unroll
        for (int k = 0; k < 8; ++k) tot += wred[k];
        mean = tot / SARV;                  // identical on all threads

        float ss = 0.f;
#pragma unroll
        for (int k = 0; k < 16; ++k) {
            float d = vals[k] - mean;
            ss += d * d;
        }
#pragma unroll
        for (int d = 16; d; d >>= 1) ss += __shfl_xor_sync(0xffffffffu, ss, d);
        if (lane == 0) wred[8 + w] = ss;
        __syncthreads();
        float stot = 0.f;
#pragma unroll
        for (int k = 0; k < 8; ++k) stot += wred[8 + k];
        ssd = stot;
    }

    // ---- vertical suffix snapshots over rows [i0-63+k, i0-1], k=4j+3 ----
    {
        float SA = 0.f, SA2 = 0.f;
        const int rtop = min(i0 - 1, H1D - 1);
        const int rbot = max(i0 - 63, 0);
        for (int r = rtop; r >= rbot; --r) {
            float a = x[r * W1D + t];
            SA  += a;
            SA2 += a * a;
            int k = r - (i0 - 63);
            if ((k & 3) == 3 && k < KROWS) snapQ[k >> 2][t] = make_float2(SA, SA2);
        }
        const int nfill = 63 - i0;          // clamped region bound (may be <0)
#pragma unroll
        for (int j = 0; j < KROWS / 4; ++j) {
            const int k = 4 * j + 3;
            if (k < nfill)            snapQ[j][t] = make_float2(SA, SA2);
            else if (k >= HO - i0)    snapQ[j][t] = make_float2(0.f, 0.f);
        }
    }
    // snapshots read only by the owner thread -> no barrier needed

    float PB = 0.f, PB2 = 0.f;   // running prefix over rows [i0, i] (add-only)

    // incremental row pointers (advance by constants each iteration)
    const bool tailv = (t < HO - 256);
    const float* xro = x + (i0 - 63) * W1D + t;          // oldest-window rows
    const float* xri = x + i0 * W1D + t;                 // entering rows
    const float* xcr = xc + (size_t)i0 * HO + t;         // xcorr row ia
    float*       opr = op + (size_t)i0 * HO + t;         // out row ia

#pragma unroll 2
    for (int kk = 0; kk < KROWS / 2; ++kk) {
        const int ia = i0 + 2 * kk;
        const int ib = ia + 1;
        const bool bvalid = (ib < HO);
        const int ra = ia - 63;             // oldest row of row-ia's window
        const bool even = ((kk & 1) == 0);  // compile-time under unroll 2

        // --- all global loads up front (MLP) ---
        float r0 = (ra >= 0) ? xro[0] : 0.f;
        float r1 = 0.f, r2 = 0.f;
        if (even) {
            if (ra + 1 >= 0) r1 = xro[W1D];
            if (ra + 2 >= 0) r2 = xro[2 * W1D];
        }
        float la = 0.f, lb = 0.f;
        if (ia < H1D) la = xri[0];
        if (ib < H1D) lb = xri[W1D];
        float xa0 = xcr[0];
        float xa1 = tailv ? xcr[256] : 0.f;
        float xb0 = 0.f, xb1 = 0.f;
        if (bvalid) {
            xb0 = xcr[HO];
            xb1 = tailv ? xcr[HO + 256] : 0.f;
        }

        // --- reconstruct the two suffix snapshots (add-only) ---
        const float2 base = snapQ[kk >> 1][t];
        float snB, snB2;
        if (even) {
            snB  = (r1 + r2) + base.x;                       // snap[4m+1]
            snB2 = fmaf(r1, r1, fmaf(r2, r2, base.y));
        } else {
            snB  = base.x;                                   // snap[4m+3]
            snB2 = base.y;
        }
        const float snA  = r0 + snB;                         // snap[k_even]
        const float snA2 = fmaf(r0, r0, snB2);

        // --- vertical windows for both rows ---
        PB  += la;
        PB2 += la * la;
        const float Va  = snA  + PB;
        const float V2a = snA2 + PB2;
        PB  += lb;
        PB2 += lb * lb;
        const float Vb  = snB  + PB;
        const float V2b = snB2 + PB2;

        // --- warp prefix scans (4 independent chains) ---
        float pa = Va, pa2 = V2a, pb = Vb, pb2 = V2b;
#pragma unroll
        for (int d = 1; d < 32; d <<= 1) {
            float u0 = __shfl_up_sync(0xffffffffu, pa,  d);
            float u1 = __shfl_up_sync(0xffffffffu, pa2, d);
            float u2 = __shfl_up_sync(0xffffffffu, pb,  d);
            float u3 = __shfl_up_sync(0xffffffffu, pb2, d);
            if (lane >= d) { pa += u0; pa2 += u1; pb += u2; pb2 += u3; }
        }
        const float totA  = __shfl_sync(0xffffffffu, pa,  31);
        const float totA2 = __shfl_sync(0xffffffffu, pa2, 31);
        const float totB  = __shfl_sync(0xffffffffu, pb,  31);
        const float totB2 = __shfl_sync(0xffffffffu, pb2, 31);
        // warp suffixes via cancellation-safe subtraction (exact at lane 31)
        float sa  = (totA  - pa)  + Va;
        float sa2 = (totA2 - pa2) + V2a;
        float sb  = (totB  - pb)  + Vb;
        float sb2 = (totB2 - pb2) + V2b;

        if (lane == 0) wtot4[w] = make_float4(totA, totA2, totB, totB2);
        __syncthreads();

        // stitch 64-col blocks (warps 2b, 2b+1)
        if (h == 1) {
            float4 q = wtot4[w - 1];
            pa += q.x; pa2 += q.y; pb += q.z; pb2 += q.w;
        } else {
            float4 q = wtot4[w + 1];
            sa += q.x; sa2 += q.y; sb += q.z; sb2 += q.w;
        }
        SvA[t] = make_float2(sa, sa2);
        SvB[t] = make_float2(sb, sb2);
        __syncthreads();

        // --- epilogue ---
        // j = t: window = own prefix (+ suffix piece when straddling blocks)
        const bool addS = (t > 63) && ((t & 63) != 63);
        {
            float ws = pa, ws2 = pa2;
            if (addS) { float2 q = SvA[t - 63]; ws += q.x; ws2 += q.y; }
            ncc_emit(opr, xa0, ws, ws2, mean, ssd);
        }
        if (bvalid) {
            float ws = pb, ws2 = pb2;
            if (addS) { float2 q = SvB[t - 63]; ws += q.x; ws2 += q.y; }
            ncc_emit(opr + HO, xb0, ws, ws2, mean, ssd);
        }
        // j = t + 256 (t < 63): always pure suffix Sv[t + 193]
        if (tailv) {
            {
                float2 q = SvA[t + 193];
                ncc_emit(opr + 256, xa1, q.x, q.y, mean, ssd);
            }
            if (bvalid) {
                float2 q = SvB[t + 193];
                ncc_emit(opr + HO + 256, xb1, q.x, q.y, mean, ssd);
            }
        }

        // advance incremental pointers
        xro += 2 * W1D;
        xri += 2 * W1D;
        xcr += 2 * HO;
        opr += 2 * HO;
        // next iteration's wtot4/Sv writes are separated from this epilogue's
        // reads by the __syncthreads after the wtot4 store above.
    }
}

// ---------------------------------------------------------------------------
extern "C" void kernel_launch(void* const* d_in, const int* in_sizes, int n_in,
                              void* d_out, int out_size) {
    const float* feat1 = nullptr;
    const float* feat2 = nullptr;
    const float* xcorr = nullptr;
    for (int i = 0; i < n_in; ++i) {
        if (in_sizes[i] == NCH * H1D * W1D)     feat1 = (const float*)d_in[i];
        else if (in_sizes[i] == NCH * TW * TW)  feat2 = (const float*)d_in[i];
        else if (in_sizes[i] == NCH * HO * HO)  xcorr = (const float*)d_in[i];
    }
    float* out = (float*)d_out;

    dim3 grid(NCHNK, NCH);
    ncc_vh11<<<grid, 256>>>(feat1, feat2, xcorr, out);
}

// round 16
// speedup vs baseline: 1.0872x; 1.0872x over previous
#include <cuda_runtime.h>

// Shapes: B=16, C=32, H1=W1=256, H2=W2=64
#define NCH   512
#define H1D   256
#define W1D   256
#define TW    64
#define HO    319                         // H1 + TW - 1
#define SARV  4096.0f
#define EPSV  1.1920928955078125e-07f     // float32 eps

#define KROWS 32
#define NCHNK ((HO + KROWS - 1) / KROWS)  // 10

// Precise sqrt/div epilogue (empirically fastest: ILP-rich FFMA expansion).
__device__ __forceinline__ void ncc_emit(float* __restrict__ op,
                                         float xv, float ws, float ws2,
                                         float mean, float ssd) {
    float num = xv - ws * mean;
    float wcr = ws2 - ws * ws * (1.0f / SARV);
    float den = sqrtf(fmaxf(wcr * ssd, 0.f));
    float r   = fmaxf(num, EPSV) / fmaxf(den, EPSV);
    *op = (den > EPSV) ? r : 0.f;
}

// ---------------------------------------------------------------------------
// R14 structure: 256 threads = 256 columns, 2 rows/iter, 32 rows per CTA,
// in-window-only sums, quarter-density vertical snapshots (k=4j+3, 16 KB),
// warp suffix via (total - prefix) + own (exact at lane 31).
// This round: Sv packed as float4 (half the MIO ops), incremental row
// pointers (fewer IMADs), hoisted tail predicate. Math bit-identical to R14.
// ---------------------------------------------------------------------------
__global__ __launch_bounds__(256, 7) void ncc_vh12(const float* __restrict__ f1,
                                                   const float* __restrict__ f2,
                                                   const float* __restrict__ xcg,
                                                   float* __restrict__ outg) {
    const int c  = blockIdx.y;
    const int i0 = blockIdx.x * KROWS;
    const int t  = threadIdx.x;
    const int lane = t & 31;
    const int w    = t >> 5;        // warp 0..7
    const int h    = w & 1;         // half within its 64-col block

    const float* __restrict__ x  = f1  + (size_t)c * (H1D * W1D);
    const float* __restrict__ p2 = f2  + (size_t)c * (TW * TW);
    const float* __restrict__ xc = xcg + (size_t)c * (HO * HO);
    float* __restrict__ op       = outg + (size_t)c * (HO * HO);

    __shared__ float  wred[16];                // warp sums / warp ssd sums
    __shared__ float2 snapQ[KROWS / 4][256];   // snapshots at k = 4j+3 only
    __shared__ float4 wtot4[8];                // per-warp totals (A,A2,B,B2)
    __shared__ float4 SvAB[256];               // packed suffixes (sa,sa2,sb,sb2)

    // ---- per-channel stats of feat_2 (warp-shfl reduction, 2 barriers) ----
    float mean, ssd;
    {
        float vals[16];
        float s = 0.f;
#pragma unroll
        for (int k = 0; k < 16; ++k) {
            vals[k] = p2[t + 256 * k];
            s += vals[k];
        }
#pragma unroll
        for (int d = 16; d; d >>= 1) s += __shfl_xor_sync(0xffffffffu, s, d);
        if (lane == 0) wred[w] = s;
        __syncthreads();
        float tot = 0.f;
#pragma unroll
        for (int k = 0; k < 8; ++k) tot += wred[k];
        mean = tot / SARV;                  // identical on all threads

        float ss = 0.f;
#pragma unroll
        for (int k = 0; k < 16; ++k) {
            float d = vals[k] - mean;
            ss += d * d;
        }
#pragma unroll
        for (int d = 16; d; d >>= 1) ss += __shfl_xor_sync(0xffffffffu, ss, d);
        if (lane == 0) wred[8 + w] = ss;
        __syncthreads();
        float stot = 0.f;
#pragma unroll
        for (int k = 0; k < 8; ++k) stot += wred[8 + k];
        ssd = stot;
    }

    // ---- vertical suffix snapshots over rows [i0-63+k, i0-1], k=4j+3 ----
    {
        float SA = 0.f, SA2 = 0.f;
        const int rtop = min(i0 - 1, H1D - 1);
        const int rbot = max(i0 - 63, 0);
        for (int r = rtop; r >= rbot; --r) {
            float a = x[r * W1D + t];
            SA  += a;
            SA2 += a * a;
            int k = r - (i0 - 63);
            if ((k & 3) == 3 && k < KROWS) snapQ[k >> 2][t] = make_float2(SA, SA2);
        }
        const int nfill = 63 - i0;          // clamped region bound (may be <0)
#pragma unroll
        for (int j = 0; j < KROWS / 4; ++j) {
            const int k = 4 * j + 3;
            if (k < nfill)            snapQ[j][t] = make_float2(SA, SA2);
            else if (k >= HO - i0)    snapQ[j][t] = make_float2(0.f, 0.f);
        }
    }
    // snapshots read only by the owner thread -> no barrier needed

    float PB = 0.f, PB2 = 0.f;   // running prefix over rows [i0, i] (add-only)

    // incremental row pointers (advance by constants each iteration)
    const bool tailv = (t < HO - 256);
    const float* xro = x + (i0 - 63) * W1D + t;          // oldest-window rows
    const float* xri = x + i0 * W1D + t;                 // entering rows
    const float* xcr = xc + (size_t)i0 * HO + t;         // xcorr row ia
    float*       opr = op + (size_t)i0 * HO + t;         // out row ia

#pragma unroll 2
    for (int kk = 0; kk < KROWS / 2; ++kk) {
        const int ia = i0 + 2 * kk;
        const int ib = ia + 1;
        const bool bvalid = (ib < HO);
        const int ra = ia - 63;             // oldest row of row-ia's window
        const bool even = ((kk & 1) == 0);  // compile-time under unroll 2

        // --- all global loads up front (MLP) ---
        float r0 = (ra >= 0) ? xro[0] : 0.f;
        float r1 = 0.f, r2 = 0.f;
        if (even) {
            if (ra + 1 >= 0) r1 = xro[W1D];
            if (ra + 2 >= 0) r2 = xro[2 * W1D];
        }
        float la = 0.f, lb = 0.f;
        if (ia < H1D) la = xri[0];
        if (ib < H1D) lb = xri[W1D];
        float xa0 = xcr[0];
        float xa1 = tailv ? xcr[256] : 0.f;
        float xb0 = 0.f, xb1 = 0.f;
        if (bvalid) {
            xb0 = xcr[HO];
            xb1 = tailv ? xcr[HO + 256] : 0.f;
        }

        // --- reconstruct the two suffix snapshots (add-only) ---
        const float2 base = snapQ[kk >> 1][t];
        float snB, snB2;
        if (even) {
            snB  = (r1 + r2) + base.x;                       // snap[4m+1]
            snB2 = fmaf(r1, r1, fmaf(r2, r2, base.y));
        } else {
            snB  = base.x;                                   // snap[4m+3]
            snB2 = base.y;
        }
        const float snA  = r0 + snB;                         // snap[k_even]
        const float snA2 = fmaf(r0, r0, snB2);

        // --- vertical windows for both rows ---
        PB  += la;
        PB2 += la * la;
        const float Va  = snA  + PB;
        const float V2a = snA2 + PB2;
        PB  += lb;
        PB2 += lb * lb;
        const float Vb  = snB  + PB;
        const float V2b = snB2 + PB2;

        // --- warp prefix scans (4 independent chains) ---
        float pa = Va, pa2 = V2a, pb = Vb, pb2 = V2b;
#pragma unroll
        for (int d = 1; d < 32; d <<= 1) {
            float u0 = __shfl_up_sync(0xffffffffu, pa,  d);
            float u1 = __shfl_up_sync(0xffffffffu, pa2, d);
            float u2 = __shfl_up_sync(0xffffffffu, pb,  d);
            float u3 = __shfl_up_sync(0xffffffffu, pb2, d);
            if (lane >= d) { pa += u0; pa2 += u1; pb += u2; pb2 += u3; }
        }
        const float totA  = __shfl_sync(0xffffffffu, pa,  31);
        const float totA2 = __shfl_sync(0xffffffffu, pa2, 31);
        const float totB  = __shfl_sync(0xffffffffu, pb,  31);
        const float totB2 = __shfl_sync(0xffffffffu, pb2, 31);
        // warp suffixes via cancellation-safe subtraction (exact at lane 31)
        float sa  = (totA  - pa)  + Va;
        float sa2 = (totA2 - pa2) + V2a;
        float sb  = (totB  - pb)  + Vb;
        float sb2 = (totB2 - pb2) + V2b;

        if (lane == 0) wtot4[w] = make_float4(totA, totA2, totB, totB2);
        __syncthreads();

        // stitch 64-col blocks (warps 2b, 2b+1)
        if (h == 1) {
            float4 q = wtot4[w - 1];
            pa += q.x; pa2 += q.y; pb += q.z; pb2 += q.w;
        } else {
            float4 q = wtot4[w + 1];
            sa += q.x; sa2 += q.y; sb += q.z; sb2 += q.w;
        }
        SvAB[t] = make_float4(sa, sa2, sb, sb2);
        __syncthreads();

        // --- epilogue ---
        // j = t: window = own prefix (+ suffix piece when straddling blocks)
        const bool addS = (t > 63) && ((t & 63) != 63);
        {
            float wsa = pa, wsa2 = pa2, wsb = pb, wsb2 = pb2;
            if (addS) {
                float4 q = SvAB[t - 63];
                wsa += q.x; wsa2 += q.y; wsb += q.z; wsb2 += q.w;
            }
            ncc_emit(opr, xa0, wsa, wsa2, mean, ssd);
            if (bvalid)
                ncc_emit(opr + HO, xb0, wsb, wsb2, mean, ssd);
        }
        // j = t + 256 (t < 63): always pure suffix Sv[t + 193]
        if (tailv) {
            float4 q = SvAB[t + 193];
            ncc_emit(opr + 256, xa1, q.x, q.y, mean, ssd);
            if (bvalid)
                ncc_emit(opr + HO + 256, xb1, q.z, q.w, mean, ssd);
        }

        // advance incremental pointers
        xro += 2 * W1D;
        xri += 2 * W1D;
        xcr += 2 * HO;
        opr += 2 * HO;
        // next iteration's wtot4/SvAB writes are separated from this
        // epilogue's reads by the __syncthreads after the wtot4 store above.
    }
}

// ---------------------------------------------------------------------------
extern "C" void kernel_launch(void* const* d_in, const int* in_sizes, int n_in,
                              void* d_out, int out_size) {
    const float* feat1 = nullptr;
    const float* feat2 = nullptr;
    const float* xcorr = nullptr;
    for (int i = 0; i < n_in; ++i) {
        if (in_sizes[i] == NCH * H1D * W1D)     feat1 = (const float*)d_in[i];
        else if (in_sizes[i] == NCH * TW * TW)  feat2 = (const float*)d_in[i];
        else if (in_sizes[i] == NCH * HO * HO)  xcorr = (const float*)d_in[i];
    }
    float* out = (float*)d_out;

    dim3 grid(NCHNK, NCH);
    ncc_vh12<<<grid, 256>>>(feat1, feat2, xcorr, out);
}

// round 17
// speedup vs baseline: 1.2395x; 1.1401x over previous
#include <cuda_runtime.h>

// Shapes: B=16, C=32, H1=W1=256, H2=W2=64
#define NCH   512
#define H1D   256
#define W1D   256
#define TW    64
#define HO    319                         // H1 + TW - 1
#define SARV  4096.0f
#define EPSV  1.1920928955078125e-07f     // float32 eps

#define KROWS 32
#define NCHNK ((HO + KROWS - 1) / KROWS)  // 10

// Precise sqrt/div epilogue (empirically fastest: ILP-rich FFMA expansion).
__device__ __forceinline__ void ncc_emit(float* __restrict__ op, size_t idx,
                                         float xv, float ws, float ws2,
                                         float mean, float ssd) {
    float num = xv - ws * mean;
    float wcr = ws2 - ws * ws * (1.0f / SARV);
    float den = sqrtf(fmaxf(wcr * ssd, 0.f));
    float r   = fmaxf(num, EPSV) / fmaxf(den, EPSV);
    op[idx] = (den > EPSV) ? r : 0.f;
}

// ---------------------------------------------------------------------------
// R14 (204.9us) verbatim except the snapshot-init loop, which is batched 4
// rows per step to overlap LDG latency (accumulation order unchanged ->
// bit-identical results). 256 threads = 256 columns, 2 rows/iter, 32 rows per
// CTA, in-window-only sums, quarter-density snapshots (k=4j+3, 16 KB), warp
// suffix via (total - prefix) + own (exact at lane 31). 8 CTAs/SM.
// ---------------------------------------------------------------------------
__global__ __launch_bounds__(256, 7) void ncc_vh13(const float* __restrict__ f1,
                                                   const float* __restrict__ f2,
                                                   const float* __restrict__ xcg,
                                                   float* __restrict__ outg) {
    const int c  = blockIdx.y;
    const int i0 = blockIdx.x * KROWS;
    const int t  = threadIdx.x;
    const int lane = t & 31;
    const int w    = t >> 5;        // warp 0..7
    const int h    = w & 1;         // half within its 64-col block

    const float* __restrict__ x  = f1  + (size_t)c * (H1D * W1D);
    const float* __restrict__ p2 = f2  + (size_t)c * (TW * TW);
    const float* __restrict__ xc = xcg + (size_t)c * (HO * HO);
    float* __restrict__ op       = outg + (size_t)c * (HO * HO);

    __shared__ float  wred[16];                // warp sums / warp ssd sums
    __shared__ float2 snapQ[KROWS / 4][256];   // snapshots at k = 4j+3 only
    __shared__ float4 wtot4[8];                // per-warp totals (A,A2,B,B2)
    __shared__ float2 SvA[256], SvB[256];      // published 64-block suffixes

    // ---- per-channel stats of feat_2 (warp-shfl reduction, 2 barriers) ----
    float mean, ssd;
    {
        float vals[16];
        float s = 0.f;
#pragma unroll
        for (int k = 0; k < 16; ++k) {
            vals[k] = p2[t + 256 * k];
            s += vals[k];
        }
#pragma unroll
        for (int d = 16; d; d >>= 1) s += __shfl_xor_sync(0xffffffffu, s, d);
        if (lane == 0) wred[w] = s;
        __syncthreads();
        float tot = 0.f;
#pragma unroll
        for (int k = 0; k < 8; ++k) tot += wred[k];
        mean = tot / SARV;                  // identical on all threads

        float ss = 0.f;
#pragma unroll
        for (int k = 0; k < 16; ++k) {
            float d = vals[k] - mean;
            ss += d * d;
        }
#pragma unroll
        for (int d = 16; d; d >>= 1) ss += __shfl_xor_sync(0xffffffffu, ss, d);
        if (lane == 0) wred[8 + w] = ss;
        __syncthreads();
        float stot = 0.f;
#pragma unroll
        for (int k = 0; k < 8; ++k) stot += wred[8 + k];
        ssd = stot;
    }

    // ---- vertical suffix snapshots over rows [i0-63+k, i0-1], k=4j+3 ----
    // Batched 4 rows/step: 4 independent LDGs issued together, applied in the
    // same descending-row order as the scalar loop (bit-identical sums).
    {
        float SA = 0.f, SA2 = 0.f;
        const int rtop = min(i0 - 1, H1D - 1);
        const int rbot = max(i0 - 63, 0);
        const int kbase = i0 - 63;
        int r = rtop;
        for (; r - 3 >= rbot; r -= 4) {
            const float a0 = x[r * W1D + t];
            const float a1 = x[(r - 1) * W1D + t];
            const float a2 = x[(r - 2) * W1D + t];
            const float a3 = x[(r - 3) * W1D + t];
            SA += a0; SA2 = fmaf(a0, a0, SA2);
            { int k = r - kbase;
              if ((k & 3) == 3 && k < KROWS) snapQ[k >> 2][t] = make_float2(SA, SA2); }
            SA += a1; SA2 = fmaf(a1, a1, SA2);
            { int k = r - 1 - kbase;
              if ((k & 3) == 3 && k < KROWS) snapQ[k >> 2][t] = make_float2(SA, SA2); }
            SA += a2; SA2 = fmaf(a2, a2, SA2);
            { int k = r - 2 - kbase;
              if ((k & 3) == 3 && k < KROWS) snapQ[k >> 2][t] = make_float2(SA, SA2); }
            SA += a3; SA2 = fmaf(a3, a3, SA2);
            { int k = r - 3 - kbase;
              if ((k & 3) == 3 && k < KROWS) snapQ[k >> 2][t] = make_float2(SA, SA2); }
        }
        for (; r >= rbot; --r) {
            const float a = x[r * W1D + t];
            SA += a; SA2 = fmaf(a, a, SA2);
            int k = r - kbase;
            if ((k & 3) == 3 && k < KROWS) snapQ[k >> 2][t] = make_float2(SA, SA2);
        }
        const int nfill = 63 - i0;          // clamped region bound (may be <0)
#pragma unroll
        for (int j = 0; j < KROWS / 4; ++j) {
            const int k = 4 * j + 3;
            if (k < nfill)            snapQ[j][t] = make_float2(SA, SA2);
            else if (k >= HO - i0)    snapQ[j][t] = make_float2(0.f, 0.f);
        }
    }
    // snapshots read only by the owner thread -> no barrier needed

    float PB = 0.f, PB2 = 0.f;   // running prefix over rows [i0, i] (add-only)

#pragma unroll 2
    for (int kk = 0; kk < KROWS / 2; ++kk) {
        const int ia = i0 + 2 * kk;
        const int ib = ia + 1;
        const bool bvalid = (ib < HO);
        const int ra = ia - 63;             // oldest row of row-ia's window
        const bool even = ((kk & 1) == 0);  // compile-time under unroll 2

        // --- all global loads up front (MLP) ---
        float r0 = (ra >= 0) ? x[ra * W1D + t] : 0.f;
        float r1 = 0.f, r2 = 0.f;
        if (even) {
            if (ra + 1 >= 0) r1 = x[(ra + 1) * W1D + t];
            if (ra + 2 >= 0) r2 = x[(ra + 2) * W1D + t];
        }
        float la = 0.f, lb = 0.f;
        if (ia < H1D) la = x[ia * W1D + t];
        if (ib < H1D) lb = x[ib * W1D + t];
        float xa0 = xc[(size_t)ia * HO + t];
        float xa1 = (t < HO - 256) ? xc[(size_t)ia * HO + 256 + t] : 0.f;
        float xb0 = 0.f, xb1 = 0.f;
        if (bvalid) {
            xb0 = xc[(size_t)ib * HO + t];
            xb1 = (t < HO - 256) ? xc[(size_t)ib * HO + 256 + t] : 0.f;
        }

        // --- reconstruct the two suffix snapshots (add-only) ---
        const float2 base = snapQ[kk >> 1][t];
        float snB, snB2;
        if (even) {
            snB  = (r1 + r2) + base.x;                       // snap[4m+1]
            snB2 = fmaf(r1, r1, fmaf(r2, r2, base.y));
        } else {
            snB  = base.x;                                   // snap[4m+3]
            snB2 = base.y;
        }
        const float snA  = r0 + snB;                         // snap[k_even]
        const float snA2 = fmaf(r0, r0, snB2);

        // --- vertical windows for both rows ---
        PB  += la;
        PB2 += la * la;
        const float Va  = snA  + PB;
        const float V2a = snA2 + PB2;
        PB  += lb;
        PB2 += lb * lb;
        const float Vb  = snB  + PB;
        const float V2b = snB2 + PB2;

        // --- warp prefix scans (4 independent chains) ---
        float pa = Va, pa2 = V2a, pb = Vb, pb2 = V2b;
#pragma unroll
        for (int d = 1; d < 32; d <<= 1) {
            float u0 = __shfl_up_sync(0xffffffffu, pa,  d);
            float u1 = __shfl_up_sync(0xffffffffu, pa2, d);
            float u2 = __shfl_up_sync(0xffffffffu, pb,  d);
            float u3 = __shfl_up_sync(0xffffffffu, pb2, d);
            if (lane >= d) { pa += u0; pa2 += u1; pb += u2; pb2 += u3; }
        }
        const float totA  = __shfl_sync(0xffffffffu, pa,  31);
        const float totA2 = __shfl_sync(0xffffffffu, pa2, 31);
        const float totB  = __shfl_sync(0xffffffffu, pb,  31);
        const float totB2 = __shfl_sync(0xffffffffu, pb2, 31);
        // warp suffixes via cancellation-safe subtraction (exact at lane 31)
        float sa  = (totA  - pa)  + Va;
        float sa2 = (totA2 - pa2) + V2a;
        float sb  = (totB  - pb)  + Vb;
        float sb2 = (totB2 - pb2) + V2b;

        if (lane == 0) wtot4[w] = make_float4(totA, totA2, totB, totB2);
        __syncthreads();

        // stitch 64-col blocks (warps 2b, 2b+1)
        if (h == 1) {
            float4 q = wtot4[w - 1];
            pa += q.x; pa2 += q.y; pb += q.z; pb2 += q.w;
        } else {
            float4 q = wtot4[w + 1];
            sa += q.x; sa2 += q.y; sb += q.z; sb2 += q.w;
        }
        SvA[t] = make_float2(sa, sa2);
        SvB[t] = make_float2(sb, sb2);
        __syncthreads();

        // --- epilogue ---
        // j = t: window = own prefix (+ suffix piece when straddling blocks)
        const bool addS = (t > 63) && ((t & 63) != 63);
        {
            float ws = pa, ws2 = pa2;
            if (addS) { float2 q = SvA[t - 63]; ws += q.x; ws2 += q.y; }
            ncc_emit(op, (size_t)ia * HO + t, xa0, ws, ws2, mean, ssd);
        }
        if (bvalid) {
            float ws = pb, ws2 = pb2;
            if (addS) { float2 q = SvB[t - 63]; ws += q.x; ws2 += q.y; }
            ncc_emit(op, (size_t)ib * HO + t, xb0, ws, ws2, mean, ssd);
        }
        // j = t + 256 (t < 63): always pure suffix Sv[t + 193]
        if (t < HO - 256) {
            {
                float2 q = SvA[t + 193];
                ncc_emit(op, (size_t)ia * HO + 256 + t, xa1, q.x, q.y, mean, ssd);
            }
            if (bvalid) {
                float2 q = SvB[t + 193];
                ncc_emit(op, (size_t)ib * HO + 256 + t, xb1, q.x, q.y, mean, ssd);
            }
        }
        // next iteration's wtot4/Sv writes are separated from this epilogue's
        // reads by the __syncthreads after the wtot4 store above.
    }
}

// ---------------------------------------------------------------------------
extern "C" void kernel_launch(void* const* d_in, const int* in_sizes, int n_in,
                              void* d_out, int out_size) {
    const float* feat1 = nullptr;
    const float* feat2 = nullptr;
    const float* xcorr = nullptr;
    for (int i = 0; i < n_in; ++i) {
        if (in_sizes[i] == NCH * H1D * W1D)     feat1 = (const float*)d_in[i];
        else if (in_sizes[i] == NCH * TW * TW)  feat2 = (const float*)d_in[i];
        else if (in_sizes[i] == NCH * HO * HO)  xcorr = (const float*)d_in[i];
    }
    float* out = (float*)d_out;

    dim3 grid(NCHNK, NCH);
    ncc_vh13<<<grid, 256>>>(feat1, feat2, xcorr, out);
}